// round 14
// baseline (speedup 1.0000x reference)
#include <cuda_runtime.h>
#include <cuda_fp16.h>
#include <cstdint>

// Problem constants
#define NROWS   200000
#define NPAD    200064        // 1563 * 128: GEMM row blocks need no bounds checks on A
#define KTOT    1280          // 256 (x) + 1024 (h_cat)

// GEMM tiling: BM=128, BN=192 (64 u | 64 o | 64 inner), 256 threads, 1 CTA/SM
#define BM      128
#define BN      192
#define BK      128           // fp16: 8 k16 MMA steps per tile, f16-chained
#define NT      (KTOT / BK)   // 10
#define NSTAGE  2

#define ROWB    272           // smem row stride bytes (128 halves = 256B + 16B pad)
#define A_BYTES (BM * ROWB)                // 34816
#define B_BYTES (BN * ROWB)                // 52224
#define STAGE_BYTES (A_BYTES + B_BYTES)    // 87040
#define SMEM_TOTAL  (NSTAGE * STAGE_BYTES) // 174080 (1 CTA/SM)
#define LDC     196           // epilogue exchange stride (floats)

// Static device scratch (allocation-free rule)
__device__ __half g_Bph[(size_t)768 * KTOT];          // packed fp16 weights [c'][k]
__device__ __half g_A[(size_t)NPAD * KTOT];           // fp16 [x | h_cat], padded rows

__device__ __forceinline__ uint32_t smem_u32(const void* p) {
    uint32_t a;
    asm("{ .reg .u64 t; cvta.to.shared.u64 t, %1; cvt.u32.u64 %0, t; }" : "=r"(a) : "l"(p));
    return a;
}

__device__ __forceinline__ void cp_async16(uint32_t dst, const void* src) {
    asm volatile("cp.async.ca.shared.global [%0], [%1], 16;" :: "r"(dst), "l"(src) : "memory");
}
#define CP_COMMIT()  asm volatile("cp.async.commit_group;" ::: "memory")
#define CP_WAIT0()   asm volatile("cp.async.wait_group 0;" ::: "memory")

__device__ __forceinline__ void ldsm_x4(uint32_t r[4], uint32_t addr) {
    asm volatile("ldmatrix.sync.aligned.m8n8.x4.shared.b16 {%0,%1,%2,%3}, [%4];"
                 : "=r"(r[0]), "=r"(r[1]), "=r"(r[2]), "=r"(r[3]) : "r"(addr));
}

// fp16-accumulate mma (rt = 2x the f32-acc form)
__device__ __forceinline__ void mma_f16h(uint32_t d[2], const uint32_t a[4],
                                         uint32_t b0, uint32_t b1) {
    asm volatile(
        "mma.sync.aligned.m16n8k16.row.col.f16.f16.f16.f16 "
        "{%0,%1}, {%2,%3,%4,%5}, {%6,%7}, {%0,%1};"
        : "+r"(d[0]), "+r"(d[1])
        : "r"(a[0]), "r"(a[1]), "r"(a[2]), "r"(a[3]), "r"(b0), "r"(b1));
}

// ---------------------------------------------------------------------------
// Kernel 0: build g_A[n] = [fp16(x[n]) | masked children from fp32 h_prev].
// ---------------------------------------------------------------------------
__global__ void gather_kernel(const float* __restrict__ x,
                              const float* __restrict__ h_prev,
                              const int*   __restrict__ child_idx,
                              const int*   __restrict__ child_mask) {
    int gid = blockIdx.x * 256 + threadIdx.x;      // over NPAD*160
    if (gid >= NPAD * 160) return;
    int n = gid / 160;
    int c = gid % 160;
    __half* dst = g_A + (size_t)n * KTOT + c * 8;
    uint4 v = make_uint4(0, 0, 0, 0);
    if (n < NROWS) {
        const float* src = nullptr;
        if (c < 32) {
            src = x + (size_t)n * 256 + c * 8;
        } else {
            int seg = (c - 32) >> 5;
            int kk  = ((c - 32) & 31) * 8;
            if (child_mask[n * 4 + seg] != 0)
                src = h_prev + (size_t)child_idx[n * 4 + seg] * 256 + kk;
        }
        if (src) {
            const float4* s = (const float4*)src;
            float4 v0 = s[0], v1 = s[1];
            __half2 h0 = __floats2half2_rn(v0.x, v0.y);
            __half2 h1 = __floats2half2_rn(v0.z, v0.w);
            __half2 h2 = __floats2half2_rn(v1.x, v1.y);
            __half2 h3 = __floats2half2_rn(v1.z, v1.w);
            v.x = *(uint32_t*)&h0; v.y = *(uint32_t*)&h1;
            v.z = *(uint32_t*)&h2; v.w = *(uint32_t*)&h3;
        }
    }
    *(uint4*)dst = v;
}

// ---------------------------------------------------------------------------
// Kernel 1: pack weights fp16, block row order (R9-proven).
//   c' = b*192 + seg*64 + jj ; output col = seg*256 + (b*64 + jj)
// ---------------------------------------------------------------------------
__global__ void pack_b_kernel(const float* __restrict__ W_ruo,
                              const float* __restrict__ U_ruo,
                              const float* __restrict__ U_u2) {
    int idx = blockIdx.x * 256 + threadIdx.x;
    if (idx >= 768 * KTOT) return;
    int cp = idx / KTOT;
    int k  = idx % KTOT;
    int b   = cp / 192;
    int r   = cp % 192;
    int seg = r / 64;
    int jj  = r % 64;
    int col = b * 64 + jj;
    float v;
    if (seg < 2) {
        int wrow = 256 + seg * 256 + col;
        v = (k < 256) ? W_ruo[wrow * 256 + k] : U_ruo[wrow * 1024 + (k - 256)];
    } else {
        v = (k < 256) ? 0.0f : U_u2[col * 1024 + (k - 256)];
    }
    g_Bph[idx] = __float2half_rn(v);
}

// ---------------------------------------------------------------------------
// Kernel 2: fp16 GEMM, f16 chains (K=128) + per-tile f32 promotion.
// grid = (4, 1563), 256 threads, 8 warps in 2x4, warp tile 64x48.
// BK=128, 2-stage cp.async pipeline, 1 CTA/SM.
// ---------------------------------------------------------------------------
__global__ __launch_bounds__(256, 1)
void gemm_kernel(const float* __restrict__ b_ruo, float* __restrict__ out) {
    extern __shared__ float smem[];
    const uint32_t sbase = smem_u32(smem);

    const int tid  = threadIdx.x;
    const int warp = tid >> 5;
    const int lane = tid & 31;
    const int wm   = warp >> 2;       // 0..1 -> 64 rows each
    const int wn   = warp & 3;        // 0..3 -> 48 cols each
    const int g    = lane >> 2;       // 0..7
    const int t4   = lane & 3;        // 0..3
    const int l15  = lane & 15;
    const int l16  = (lane >> 4) & 1;

    const int rowBase = blockIdx.y * BM;
    const int c0      = blockIdx.x * BN;   // g_Bph row base

    // --- A: thread owns row tid>>1, k-offset (tid&1)*64 halves (8 chunks) ---
    const int aRow = tid >> 1;
    const __half* aBase = g_A + (size_t)(rowBase + aRow) * KTOT + (tid & 1) * 64;
    const uint32_t aDst0 = sbase + aRow * ROWB + (tid & 1) * 128;
    // --- B: thread owns rows (tid>>3)+32j (j<6), chunks (tid&7) and (tid&7)+8 ---
    const int bRow = tid >> 3;
    const int bCh  = tid & 7;
    const __half* bBase = g_Bph + (size_t)(c0 + bRow) * KTOT + bCh * 8;
    const uint32_t bDst0 = sbase + A_BYTES + bRow * ROWB + bCh * 16;

    float acc[4][6][4];
#pragma unroll
    for (int mt = 0; mt < 4; mt++)
#pragma unroll
        for (int nt = 0; nt < 6; nt++)
#pragma unroll
            for (int i = 0; i < 4; i++) acc[mt][nt][i] = 0.0f;

    auto loadA = [&](int t, int s) {
        const __half*  src = aBase + t * BK;
        const uint32_t dst = aDst0 + s * STAGE_BYTES;
#pragma unroll
        for (int j = 0; j < 8; j++) cp_async16(dst + j * 16, src + j * 8);
    };

    auto loadB = [&](int t, int s) {
        const __half*  src = bBase + t * BK;
        const uint32_t dst = bDst0 + s * STAGE_BYTES;
#pragma unroll
        for (int j = 0; j < 6; j++) {
            cp_async16(dst + j * 32 * ROWB,       src + (size_t)j * 32 * KTOT);
            cp_async16(dst + j * 32 * ROWB + 128, src + (size_t)j * 32 * KTOT + 64);
        }
    };

    // ldmatrix lane bases (stage 0; add s*STAGE_BYTES)
    const uint32_t aFrag0 = sbase + (wm * 64 + l15) * ROWB + l16 * 16;
    const uint32_t bFrag0 = sbase + A_BYTES + (wn * 48 + l15) * ROWB + l16 * 16;

    auto compute = [&](int s) {
        const uint32_t aF = aFrag0 + s * STAGE_BYTES;
        const uint32_t bF = bFrag0 + s * STAGE_BYTES;
        uint32_t acch[4][6][2];           // f16 accumulators for this tile's chain
#pragma unroll
        for (int mt = 0; mt < 4; mt++)
#pragma unroll
            for (int nt = 0; nt < 6; nt++) { acch[mt][nt][0] = 0u; acch[mt][nt][1] = 0u; }
#pragma unroll
        for (int ks = 0; ks < 8; ks++) {
            uint32_t b[3][4];
#pragma unroll
            for (int p = 0; p < 3; p++)
                ldsm_x4(b[p], bF + p * (16 * ROWB) + ks * 32);
#pragma unroll
            for (int mt = 0; mt < 4; mt++) {
                uint32_t a[4];
                ldsm_x4(a, aF + mt * (16 * ROWB) + ks * 32);
#pragma unroll
                for (int p = 0; p < 3; p++) {
                    mma_f16h(acch[mt][2 * p],     a, b[p][0], b[p][2]);
                    mma_f16h(acch[mt][2 * p + 1], a, b[p][1], b[p][3]);
                }
            }
        }
        // Promote this tile's f16 partials into the f32 master accumulators
#pragma unroll
        for (int mt = 0; mt < 4; mt++)
#pragma unroll
            for (int nt = 0; nt < 6; nt++) {
                float2 lo = __half22float2(*(__half2*)&acch[mt][nt][0]);
                float2 hi = __half22float2(*(__half2*)&acch[mt][nt][1]);
                acc[mt][nt][0] += lo.x; acc[mt][nt][1] += lo.y;
                acc[mt][nt][2] += hi.x; acc[mt][nt][3] += hi.y;
            }
    };

    // --- 2-stage pipeline ---
    loadA(0, 0); loadB(0, 0); CP_COMMIT();
    for (int t = 0; t < NT; t++) {
        CP_WAIT0();
        __syncthreads();
        if (t + 1 < NT) {
            loadA(t + 1, (t + 1) & 1);
            loadB(t + 1, (t + 1) & 1);
            CP_COMMIT();
        }
        compute(t & 1);
    }

    // --- Epilogue: two half-passes through smem, fused GRU math ---
    __syncthreads();
    float* Cs = smem;                   // 64 x LDC floats = 50176 B per pass
    const int bcol = blockIdx.x * 64;
#pragma unroll
    for (int p = 0; p < 2; p++) {
        if (wm == p) {
#pragma unroll
            for (int mt = 0; mt < 4; mt++) {
                const int r = mt * 16 + g;
#pragma unroll
                for (int nt = 0; nt < 6; nt++) {
                    const int c = wn * 48 + nt * 8 + 2 * t4;
                    *(float2*)&Cs[r * LDC + c]       = make_float2(acc[mt][nt][0], acc[mt][nt][1]);
                    *(float2*)&Cs[(r + 8) * LDC + c] = make_float2(acc[mt][nt][2], acc[mt][nt][3]);
                }
            }
        }
        __syncthreads();
#pragma unroll
        for (int it = 0; it < 4; it++) {
            const int lin = it * 256 + tid;   // 64 rows x 16 quads
            const int row = lin >> 4;
            const int jj  = (lin & 15) * 4;
            const int n   = rowBase + p * 64 + row;
            float4 u4 = *(const float4*)&Cs[row * LDC + jj];
            float4 o4 = *(const float4*)&Cs[row * LDC + 64 + jj];
            float4 i4 = *(const float4*)&Cs[row * LDC + 128 + jj];
            float4 bu = *(const float4*)(b_ruo + 256 + bcol + jj);
            float4 bo = *(const float4*)(b_ruo + 512 + bcol + jj);
            float4 res;
#pragma unroll
            for (int c = 0; c < 4; c++) {
                float u = (&u4.x)[c] + (&bu.x)[c];
                float o = (&o4.x)[c] + (&bo.x)[c];
                float h = (&i4.x)[c];
                u = 1.0f / (1.0f + __expf(-u));
                o = tanhf(o);
                (&res.x)[c] = o * u + (1.0f - u) * h;
            }
            if (n < NROWS)
                *(float4*)(out + (size_t)n * 256 + bcol + jj) = res;
        }
        __syncthreads();
    }
}

// ---------------------------------------------------------------------------
extern "C" void kernel_launch(void* const* d_in, const int* in_sizes, int n_in,
                              void* d_out, int out_size) {
    const float* x          = (const float*)d_in[0];
    const float* h_prev     = (const float*)d_in[1];
    const float* W_ruo      = (const float*)d_in[2];
    const float* U_ruo      = (const float*)d_in[3];
    const float* b_ruo      = (const float*)d_in[4];
    const float* U_u2       = (const float*)d_in[5];
    const int*   child_idx  = (const int*)d_in[6];
    const int*   child_mask = (const int*)d_in[7];
    float*       out        = (float*)d_out;

    cudaFuncSetAttribute(gemm_kernel, cudaFuncAttributeMaxDynamicSharedMemorySize, SMEM_TOTAL);

    gather_kernel<<<(NPAD * 160 + 255) / 256, 256>>>(x, h_prev, child_idx, child_mask);

    pack_b_kernel<<<(768 * KTOT + 255) / 256, 256>>>(W_ruo, U_ruo, U_u2);

    dim3 grid(4, (NROWS + BM - 1) / BM);   // (4, 1563)
    gemm_kernel<<<grid, 256, SMEM_TOTAL>>>(b_ruo, out);
}

// round 15
// speedup vs baseline: 1.2391x; 1.2391x over previous
#include <cuda_runtime.h>
#include <cuda_fp16.h>
#include <cstdint>

// Problem constants
#define NROWS   200000
#define NPAD    200064        // 1563 * 128: GEMM row blocks need no bounds checks on A
#define KTOT    1280          // 256 (x) + 1024 (h_cat)

// GEMM tiling: BM=128, BN=192 (64 u | 64 o | 64 inner), 256 threads, 1 CTA/SM
#define BM      128
#define BN      192
#define BK      64            // fp16: 4 k16 MMA steps per tile; f16 chains span 2 tiles
#define NT      (KTOT / BK)   // 20
#define NSTAGE  4

#define ROWB    144           // smem row stride bytes (64 halves = 128B + 16B pad)
#define A_BYTES (BM * ROWB)                // 18432
#define B_BYTES (BN * ROWB)                // 27648
#define STAGE_BYTES (A_BYTES + B_BYTES)    // 46080
#define SMEM_TOTAL  (NSTAGE * STAGE_BYTES) // 184320 (1 CTA/SM)
#define LDC     196           // epilogue exchange stride (floats)

// Static device scratch (allocation-free rule)
__device__ __half g_Bph[(size_t)768 * KTOT];          // packed fp16 weights [c'][k]
__device__ __half g_A[(size_t)NPAD * KTOT];           // fp16 [x | h_cat], padded rows

__device__ __forceinline__ uint32_t smem_u32(const void* p) {
    uint32_t a;
    asm("{ .reg .u64 t; cvta.to.shared.u64 t, %1; cvt.u32.u64 %0, t; }" : "=r"(a) : "l"(p));
    return a;
}

__device__ __forceinline__ void cp_async16(uint32_t dst, const void* src) {
    asm volatile("cp.async.ca.shared.global [%0], [%1], 16;" :: "r"(dst), "l"(src) : "memory");
}
#define CP_COMMIT()  asm volatile("cp.async.commit_group;" ::: "memory")
#define CP_WAIT2()   asm volatile("cp.async.wait_group 2;" ::: "memory")

__device__ __forceinline__ void ldsm_x4(uint32_t r[4], uint32_t addr) {
    asm volatile("ldmatrix.sync.aligned.m8n8.x4.shared.b16 {%0,%1,%2,%3}, [%4];"
                 : "=r"(r[0]), "=r"(r[1]), "=r"(r[2]), "=r"(r[3]) : "r"(addr));
}

// fp16-accumulate mma (rt = 2x the f32-acc form)
__device__ __forceinline__ void mma_f16h(uint32_t d[2], const uint32_t a[4],
                                         uint32_t b0, uint32_t b1) {
    asm volatile(
        "mma.sync.aligned.m16n8k16.row.col.f16.f16.f16.f16 "
        "{%0,%1}, {%2,%3,%4,%5}, {%6,%7}, {%0,%1};"
        : "+r"(d[0]), "+r"(d[1])
        : "r"(a[0]), "r"(a[1]), "r"(a[2]), "r"(a[3]), "r"(b0), "r"(b1));
}

// ---------------------------------------------------------------------------
// Kernel 0: build g_A[n] = [fp16(x[n]) | masked children from fp32 h_prev].
// ---------------------------------------------------------------------------
__global__ void gather_kernel(const float* __restrict__ x,
                              const float* __restrict__ h_prev,
                              const int*   __restrict__ child_idx,
                              const int*   __restrict__ child_mask) {
    int gid = blockIdx.x * 256 + threadIdx.x;      // over NPAD*160
    if (gid >= NPAD * 160) return;
    int n = gid / 160;
    int c = gid % 160;
    __half* dst = g_A + (size_t)n * KTOT + c * 8;
    uint4 v = make_uint4(0, 0, 0, 0);
    if (n < NROWS) {
        const float* src = nullptr;
        if (c < 32) {
            src = x + (size_t)n * 256 + c * 8;
        } else {
            int seg = (c - 32) >> 5;
            int kk  = ((c - 32) & 31) * 8;
            if (child_mask[n * 4 + seg] != 0)
                src = h_prev + (size_t)child_idx[n * 4 + seg] * 256 + kk;
        }
        if (src) {
            const float4* s = (const float4*)src;
            float4 v0 = s[0], v1 = s[1];
            __half2 h0 = __floats2half2_rn(v0.x, v0.y);
            __half2 h1 = __floats2half2_rn(v0.z, v0.w);
            __half2 h2 = __floats2half2_rn(v1.x, v1.y);
            __half2 h3 = __floats2half2_rn(v1.z, v1.w);
            v.x = *(uint32_t*)&h0; v.y = *(uint32_t*)&h1;
            v.z = *(uint32_t*)&h2; v.w = *(uint32_t*)&h3;
        }
    }
    *(uint4*)dst = v;
}

// ---------------------------------------------------------------------------
// Kernel 1: pack weights fp16, block row order.
//   c' = b*192 + seg*64 + jj ; output col = seg*256 + (b*64 + jj)
// ---------------------------------------------------------------------------
__global__ void pack_b_kernel(const float* __restrict__ W_ruo,
                              const float* __restrict__ U_ruo,
                              const float* __restrict__ U_u2) {
    int idx = blockIdx.x * 256 + threadIdx.x;
    if (idx >= 768 * KTOT) return;
    int cp = idx / KTOT;
    int k  = idx % KTOT;
    int b   = cp / 192;
    int r   = cp % 192;
    int seg = r / 64;
    int jj  = r % 64;
    int col = b * 64 + jj;
    float v;
    if (seg < 2) {
        int wrow = 256 + seg * 256 + col;
        v = (k < 256) ? W_ruo[wrow * 256 + k] : U_ruo[wrow * 1024 + (k - 256)];
    } else {
        v = (k < 256) ? 0.0f : U_u2[col * 1024 + (k - 256)];
    }
    g_Bph[idx] = __float2half_rn(v);
}

// ---------------------------------------------------------------------------
// Kernel 2: fp16 GEMM, f16 chains spanning 2 tiles (K=128) + f32 promotion.
// grid = (4, 1563), 256 threads, 8 warps in 2x4, warp tile 64x48.
// BK=64, 4-stage cp.async pipeline (R13-proven), 1 CTA/SM.
// ---------------------------------------------------------------------------
__global__ __launch_bounds__(256, 1)
void gemm_kernel(const float* __restrict__ b_ruo, float* __restrict__ out) {
    extern __shared__ float smem[];
    const uint32_t sbase = smem_u32(smem);

    const int tid  = threadIdx.x;
    const int warp = tid >> 5;
    const int lane = tid & 31;
    const int wm   = warp >> 2;       // 0..1 -> 64 rows each
    const int wn   = warp & 3;        // 0..3 -> 48 cols each
    const int g    = lane >> 2;       // 0..7
    const int t4   = lane & 3;        // 0..3
    const int l15  = lane & 15;
    const int l16  = (lane >> 4) & 1;

    const int rowBase = blockIdx.y * BM;
    const int c0      = blockIdx.x * BN;   // g_Bph row base

    // --- A pointers: thread owns row tid>>1, k-offset (tid&1)*32 halves ---
    const int aRow = tid >> 1;
    const __half* aBase = g_A + (size_t)(rowBase + aRow) * KTOT + (tid & 1) * 32;
    const __half* bBase = g_Bph + (size_t)(c0 + (tid >> 3)) * KTOT + (tid & 7) * 8;
    const uint32_t aDst0 = sbase + aRow * ROWB + (tid & 1) * 64;
    const uint32_t bDst0 = sbase + A_BYTES + (tid >> 3) * ROWB + (tid & 7) * 16;

    float acc[4][6][4];
    uint32_t acch[4][6][2];               // f16 chain accumulators (2-tile span)
#pragma unroll
    for (int mt = 0; mt < 4; mt++)
#pragma unroll
        for (int nt = 0; nt < 6; nt++) {
#pragma unroll
            for (int i = 0; i < 4; i++) acc[mt][nt][i] = 0.0f;
            acch[mt][nt][0] = 0u; acch[mt][nt][1] = 0u;
        }

    auto loadA = [&](int t, int s) {
        const __half*  src = aBase + t * BK;
        const uint32_t dst = aDst0 + s * STAGE_BYTES;
#pragma unroll
        for (int j = 0; j < 4; j++) cp_async16(dst + j * 16, src + j * 8);
    };

    auto loadB = [&](int t, int s) {
        const __half*  src = bBase + t * BK;
        const uint32_t dst = bDst0 + s * STAGE_BYTES;
#pragma unroll
        for (int j = 0; j < 6; j++)
            cp_async16(dst + j * 32 * ROWB, src + (size_t)j * 32 * KTOT);
    };

    // ldmatrix lane bases (stage 0; add s*STAGE_BYTES)
    const uint32_t aFrag0 = sbase + (wm * 64 + l15) * ROWB + l16 * 16;
    const uint32_t bFrag0 = sbase + A_BYTES + (wn * 48 + l15) * ROWB + l16 * 16;

    // Accumulate one BK=64 tile into the running f16 chains.
    auto computeChain = [&](int s) {
        const uint32_t aF = aFrag0 + s * STAGE_BYTES;
        const uint32_t bF = bFrag0 + s * STAGE_BYTES;
#pragma unroll
        for (int ks = 0; ks < 4; ks++) {
            uint32_t b[3][4];
#pragma unroll
            for (int p = 0; p < 3; p++)
                ldsm_x4(b[p], bF + p * (16 * ROWB) + ks * 32);
#pragma unroll
            for (int mt = 0; mt < 4; mt++) {
                uint32_t a[4];
                ldsm_x4(a, aF + mt * (16 * ROWB) + ks * 32);
#pragma unroll
                for (int p = 0; p < 3; p++) {
                    mma_f16h(acch[mt][2 * p],     a, b[p][0], b[p][2]);
                    mma_f16h(acch[mt][2 * p + 1], a, b[p][1], b[p][3]);
                }
            }
        }
    };

    // Promote f16 chains into f32 masters and reset the chains.
    auto promote = [&]() {
#pragma unroll
        for (int mt = 0; mt < 4; mt++)
#pragma unroll
            for (int nt = 0; nt < 6; nt++) {
                float2 lo = __half22float2(*(__half2*)&acch[mt][nt][0]);
                float2 hi = __half22float2(*(__half2*)&acch[mt][nt][1]);
                acc[mt][nt][0] += lo.x; acc[mt][nt][1] += lo.y;
                acc[mt][nt][2] += hi.x; acc[mt][nt][3] += hi.y;
                acch[mt][nt][0] = 0u;   acch[mt][nt][1] = 0u;
            }
    };

    // --- 4-stage pipeline, loads issued 3 tiles ahead (R13-proven) ---
#pragma unroll
    for (int s = 0; s < NSTAGE - 1; s++) {
        loadA(s, s); loadB(s, s); CP_COMMIT();
    }
    for (int t = 0; t < NT; t++) {
        CP_WAIT2();                       // tile t's group complete
        __syncthreads();                  // all warps past compute(t-1)
        const int lt = t + NSTAGE - 1;
        if (lt < NT) {
            loadA(lt, lt & 3);
            loadB(lt, lt & 3);
        }
        CP_COMMIT();                      // exactly one group per iteration
        computeChain(t & 3);
        if (t & 1) promote();             // chain spans 2 tiles (K=128); NT even
    }

    // --- Epilogue: two half-passes through smem, fused GRU math ---
    __syncthreads();
    float* Cs = smem;                   // 64 x LDC floats = 50176 B per pass
    const int bcol = blockIdx.x * 64;
#pragma unroll
    for (int p = 0; p < 2; p++) {
        if (wm == p) {
#pragma unroll
            for (int mt = 0; mt < 4; mt++) {
                const int r = mt * 16 + g;
#pragma unroll
                for (int nt = 0; nt < 6; nt++) {
                    const int c = wn * 48 + nt * 8 + 2 * t4;
                    *(float2*)&Cs[r * LDC + c]       = make_float2(acc[mt][nt][0], acc[mt][nt][1]);
                    *(float2*)&Cs[(r + 8) * LDC + c] = make_float2(acc[mt][nt][2], acc[mt][nt][3]);
                }
            }
        }
        __syncthreads();
#pragma unroll
        for (int it = 0; it < 4; it++) {
            const int lin = it * 256 + tid;   // 64 rows x 16 quads
            const int row = lin >> 4;
            const int jj  = (lin & 15) * 4;
            const int n   = rowBase + p * 64 + row;
            float4 u4 = *(const float4*)&Cs[row * LDC + jj];
            float4 o4 = *(const float4*)&Cs[row * LDC + 64 + jj];
            float4 i4 = *(const float4*)&Cs[row * LDC + 128 + jj];
            float4 bu = *(const float4*)(b_ruo + 256 + bcol + jj);
            float4 bo = *(const float4*)(b_ruo + 512 + bcol + jj);
            float4 res;
#pragma unroll
            for (int c = 0; c < 4; c++) {
                float u = (&u4.x)[c] + (&bu.x)[c];
                float o = (&o4.x)[c] + (&bo.x)[c];
                float h = (&i4.x)[c];
                u = 1.0f / (1.0f + __expf(-u));
                o = tanhf(o);
                (&res.x)[c] = o * u + (1.0f - u) * h;
            }
            if (n < NROWS)
                *(float4*)(out + (size_t)n * 256 + bcol + jj) = res;
        }
        __syncthreads();
    }
}

// ---------------------------------------------------------------------------
extern "C" void kernel_launch(void* const* d_in, const int* in_sizes, int n_in,
                              void* d_out, int out_size) {
    const float* x          = (const float*)d_in[0];
    const float* h_prev     = (const float*)d_in[1];
    const float* W_ruo      = (const float*)d_in[2];
    const float* U_ruo      = (const float*)d_in[3];
    const float* b_ruo      = (const float*)d_in[4];
    const float* U_u2       = (const float*)d_in[5];
    const int*   child_idx  = (const int*)d_in[6];
    const int*   child_mask = (const int*)d_in[7];
    float*       out        = (float*)d_out;

    cudaFuncSetAttribute(gemm_kernel, cudaFuncAttributeMaxDynamicSharedMemorySize, SMEM_TOTAL);

    gather_kernel<<<(NPAD * 160 + 255) / 256, 256>>>(x, h_prev, child_idx, child_mask);

    pack_b_kernel<<<(768 * KTOT + 255) / 256, 256>>>(W_ruo, U_ruo, U_u2);

    dim3 grid(4, (NROWS + BM - 1) / BM);   // (4, 1563)
    gemm_kernel<<<grid, 256, SMEM_TOTAL>>>(b_ruo, out);
}